// round 13
// baseline (speedup 1.0000x reference)
#include <cuda_runtime.h>
#include <cuda_bf16.h>
#include <float.h>

// ROI pooling: crop_and_resize (bilinear, 14x14) + 2x2 max pool -> (N,7,7,512)
// feature_map: (1, 50, 75, 512) fp32 NHWC ; rois: (N,4) [x1,y1,x2,y2] ; img_size: (2,) int32
//
// grid = (7 pooled columns, N rois), block = 128 threads (one float4 of channels/thread).
// Each block fixes its 2 x-samples (4 columns) and walks feature rows frStart..frEnd
// step 1, SOFTWARE-PIPELINED: row fr+1's 4 LDG.128 issue before row fr's compute,
// so 8 loads/thread are in flight. Crop rows emit (vertical lerp of h_prev/h_cur)
// when the walk reaches their ceil feature row; emissions are in order, so one
// pending register pair implements the 2x2 max pool. Uniform scalar bookkeeping.

#define FH 50
#define FW 75
#define FC 512
#define NPOOL 7
#define CROPDIM 14
#define C4 (FC / 4)
#define ROWSTRIDE (FW * C4)

__device__ __forceinline__ float4 lerp4(const float4 a, const float4 b,
                                        const float wa, const float wb) {
    float4 h;
    h.x = fmaf(b.x, wb, a.x * wa);
    h.y = fmaf(b.y, wb, a.y * wa);
    h.z = fmaf(b.z, wb, a.z * wa);
    h.w = fmaf(b.w, wb, a.w * wa);
    return h;
}

__device__ __forceinline__ float4 max4(const float4 a, const float4 b) {
    float4 m;
    m.x = fmaxf(a.x, b.x);
    m.y = fmaxf(a.y, b.y);
    m.z = fmaxf(a.z, b.z);
    m.w = fmaxf(a.w, b.w);
    return m;
}

// per-crop-row uniform info: floor/ceil feature rows + gated lerp weights
__device__ __forceinline__ void tinfo(const int t, const float sy, const float yb,
                                      const float fh,
                                      int& rA, int& rB, float& wP, float& wC) {
    const float ys = fmaf((float)t, sy, yb);
    const float gy = ((ys >= 0.0f) && (ys <= fh)) ? 1.0f : 0.0f;
    const float fl = floorf(ys);
    const float wy = ys - fl;
    int a = min(max((int)fl, 0), FH - 1);
    int b = min(a + 1, FH - 1);
    const float wyg   = wy * gy;
    const float omwyg = (1.0f - wy) * gy;
    rA = a; rB = b;
    if (a == b) { wP = 0.0f; wC = wyg + omwyg; }   // clamped: both taps same row
    else        { wP = omwyg; wC = wyg; }
}

__global__ __launch_bounds__(128) void roi_pool_kernel(
    const float* __restrict__ fmap,
    const float* __restrict__ rois,
    const int*   __restrict__ img_size,
    float*       __restrict__ out)
{
    const int px  = blockIdx.x;   // pooled column 0..6
    const int n   = blockIdx.y;   // roi index
    const int tid = threadIdx.x;  // float4 channel chunk 0..127

    // ---- uniform per-block scalar setup ----
    const float ih = (float)img_size[0] - 1.0f;   // 799
    const float iw = (float)img_size[1] - 1.0f;   // 1199
    const float4 r = reinterpret_cast<const float4*>(rois)[n]; // x1,y1,x2,y2
    const float bx1 = r.x / iw;
    const float by1 = r.y / ih;
    const float bx2 = r.z / iw;
    const float by2 = r.w / ih;

    const float fh = (float)(FH - 1);   // 49
    const float fw = (float)(FW - 1);   // 74
    const float sy = (by2 - by1) * fh * (1.0f / (CROPDIM - 1));
    const float sx = (bx2 - bx1) * fw * (1.0f / (CROPDIM - 1));
    const float yb = by1 * fh;
    const float xb = bx1 * fw;

    // ---- the block's 2 x-samples (4 column offsets, uniform) ----
    int   cA0, cB0, cA1, cB1;
    float wx0, omwx0, wx1, omwx1;
    {
        const float xs0 = fmaf((float)(2 * px), sx, xb);
        const float gx0 = ((xs0 >= 0.0f) && (xs0 <= fw)) ? 1.0f : 0.0f;
        const float f0 = floorf(xs0);
        int xi0 = min(max((int)f0, 0), FW - 1);
        cA0 = xi0 * C4;  cB0 = min(xi0 + 1, FW - 1) * C4;
        wx0 = (xs0 - f0) * gx0;  omwx0 = (1.0f - (xs0 - f0)) * gx0;

        const float xs1 = fmaf((float)(2 * px + 1), sx, xb);
        const float gx1 = ((xs1 >= 0.0f) && (xs1 <= fw)) ? 1.0f : 0.0f;
        const float f1 = floorf(xs1);
        int xi1 = min(max((int)f1, 0), FW - 1);
        cA1 = xi1 * C4;  cB1 = min(xi1 + 1, FW - 1) * C4;
        wx1 = (xs1 - f1) * gx1;  omwx1 = (1.0f - (xs1 - f1)) * gx1;
    }

    const float4* __restrict__ fb = reinterpret_cast<const float4*>(fmap) + tid;
    float4* __restrict__ ob = reinterpret_cast<float4*>(out)
        + ((long)n * (NPOOL * NPOOL) + px) * C4 + tid;

    // ---- crop-row bookkeeping (uniform) ----
    int   tptr = 0;
    int   trA, trB;
    float twP, twC;
    tinfo(0, sy, yb, fh, trA, trB, twP, twC);
    int eA, eB; float ewP, ewC;
    tinfo(CROPDIM - 1, sy, yb, fh, eA, eB, ewP, ewC);
    const int frEnd = eB;
    int fr = trA;

    // ---- prologue: load first row ----
    const float4* rp0 = fb + fr * ROWSTRIDE;
    float4 La0 = __ldg(rp0 + cA0);
    float4 La1 = __ldg(rp0 + cB0);
    float4 La2 = __ldg(rp0 + cA1);
    float4 La3 = __ldg(rp0 + cB1);

    float4 hp0 = make_float4(0.f, 0.f, 0.f, 0.f);
    float4 hp1 = hp0;
    float4 pend0 = hp0, pend1 = hp0;

    // ---- pipelined y walk ----
    while (fr <= frEnd) {
        // prefetch next row (clamped address; harmless overrun on last iter)
        const int frn = min(fr + 1, frEnd);
        const float4* rq = fb + frn * ROWSTRIDE;
        const float4 Lb0 = __ldg(rq + cA0);
        const float4 Lb1 = __ldg(rq + cB0);
        const float4 Lb2 = __ldg(rq + cA1);
        const float4 Lb3 = __ldg(rq + cB1);

        // compute current row's horizontal lerps
        const float4 h0 = lerp4(La0, La1, omwx0, wx0);
        const float4 h1 = lerp4(La2, La3, omwx1, wx1);

        // emit every crop row whose ceil feature row is fr (in t order)
        while (tptr < CROPDIM && trB == fr) {
            const float4 v0 = lerp4(hp0, h0, twP, twC);
            const float4 v1 = lerp4(hp1, h1, twP, twC);
            if ((tptr & 1) == 0) {
                pend0 = v0;  pend1 = v1;
            } else {
                ob[(tptr >> 1) * (NPOOL * C4)] =
                    max4(max4(pend0, v0), max4(pend1, v1));
            }
            tptr++;
            if (tptr < CROPDIM) tinfo(tptr, sy, yb, fh, trA, trB, twP, twC);
        }
        if (tptr >= CROPDIM) break;

        hp0 = h0;  hp1 = h1;
        La0 = Lb0; La1 = Lb1; La2 = Lb2; La3 = Lb3;
        fr++;
    }
}

extern "C" void kernel_launch(void* const* d_in, const int* in_sizes, int n_in,
                              void* d_out, int out_size) {
    const float* fmap     = (const float*)d_in[0];
    const float* rois     = (const float*)d_in[1];
    const int*   img_size = (const int*)d_in[2];
    float* out = (float*)d_out;

    const int N = in_sizes[1] / 4;   // number of rois
    dim3 grid(NPOOL, N);
    roi_pool_kernel<<<grid, 128>>>(fmap, rois, img_size, out);
}

// round 14
// speedup vs baseline: 1.3953x; 1.3953x over previous
#include <cuda_runtime.h>
#include <cuda_bf16.h>
#include <float.h>

// ROI pooling: crop_and_resize (bilinear, 14x14) + 2x2 max pool -> (N,7,7,512)
// feature_map: (1, 50, 75, 512) fp32 NHWC ; rois: (N,4) [x1,y1,x2,y2] ; img_size: (2,) int32
//
// grid = (7 pooled rows, N rois)  [py fastest: the 7 blocks of a roi are adjacent
// in launch order and share feature rows -> L1/L2 temporal locality],
// block = 128 threads (one float4 of channels per thread).
// Horizontal-lerp-per-feature-row then vertical lerp; shared middle feature row
// (rowB[0]==rowT[1], ~70% of blocks, uniform condition) reuses loads + h-lerp ->
// 6 instead of 8 loads per sample. Streaming stores (__stcs) for the write-only
// output keep the L2-resident feature map undisturbed. Mask folded into weights.

#define FH 50
#define FW 75
#define FC 512
#define NPOOL 7
#define CROPDIM 14
#define C4 (FC / 4)
#define ROWSTRIDE (FW * C4)

__device__ __forceinline__ float4 lerp4(const float4 a, const float4 b,
                                        const float wa, const float wb) {
    float4 h;
    h.x = fmaf(b.x, wb, a.x * wa);
    h.y = fmaf(b.y, wb, a.y * wa);
    h.z = fmaf(b.z, wb, a.z * wa);
    h.w = fmaf(b.w, wb, a.w * wa);
    return h;
}

__device__ __forceinline__ void maxacc4(float4& m, const float4 a, const float4 b) {
    m.x = fmaxf(m.x, fmaxf(a.x, b.x));
    m.y = fmaxf(m.y, fmaxf(a.y, b.y));
    m.z = fmaxf(m.z, fmaxf(a.z, b.z));
    m.w = fmaxf(m.w, fmaxf(a.w, b.w));
}

__global__ __launch_bounds__(128) void roi_pool_kernel(
    const float* __restrict__ fmap,
    const float* __restrict__ rois,
    const int*   __restrict__ img_size,
    float*       __restrict__ out)
{
    const int py = blockIdx.x;   // pooled row 0..6 (fastest -> same-roi adjacency)
    const int n  = blockIdx.y;   // roi index
    const int c4 = threadIdx.x;  // float4 channel chunk 0..127

    // ---- uniform per-block scalar setup ----
    const float ih = (float)img_size[0] - 1.0f;   // 799
    const float iw = (float)img_size[1] - 1.0f;   // 1199
    const float4 r = reinterpret_cast<const float4*>(rois)[n]; // x1,y1,x2,y2
    const float bx1 = r.x / iw;
    const float by1 = r.y / ih;
    const float bx2 = r.z / iw;
    const float by2 = r.w / ih;

    const float fh = (float)(FH - 1);   // 49
    const float fw = (float)(FW - 1);   // 74
    const float sy = (by2 - by1) * fh * (1.0f / (CROPDIM - 1));
    const float sx = (bx2 - bx1) * fw * (1.0f / (CROPDIM - 1));
    const float yb = by1 * fh;
    const float xb = bx1 * fw;

    // two crop rows feeding this pooled row (uniform scalars)
    int   row0, row1, row2, row3;
    float wyg0, omwyg0, wyg1, omwyg1;
    {
        const float ys0 = fmaf((float)(2 * py), sy, yb);
        const float gy0 = ((ys0 >= 0.0f) && (ys0 <= fh)) ? 1.0f : 0.0f;
        const float fl0 = floorf(ys0);
        const float wy0 = ys0 - fl0;
        int yi0 = min(max((int)fl0, 0), FH - 1);
        row0 = yi0 * ROWSTRIDE;
        row1 = min(yi0 + 1, FH - 1) * ROWSTRIDE;
        wyg0 = wy0 * gy0;  omwyg0 = (1.0f - wy0) * gy0;

        const float ys1 = fmaf((float)(2 * py + 1), sy, yb);
        const float gy1 = ((ys1 >= 0.0f) && (ys1 <= fh)) ? 1.0f : 0.0f;
        const float fl1 = floorf(ys1);
        const float wy1 = ys1 - fl1;
        int yi1 = min(max((int)fl1, 0), FH - 1);
        row2 = yi1 * ROWSTRIDE;
        row3 = min(yi1 + 1, FH - 1) * ROWSTRIDE;
        wyg1 = wy1 * gy1;  omwyg1 = (1.0f - wy1) * gy1;
    }
    const bool shared_row = (row2 == row1);   // uniform across the block

    const float4* __restrict__ fb = reinterpret_cast<const float4*>(fmap) + c4;
    float4* __restrict__ ob = reinterpret_cast<float4*>(out)
        + ((long)n * (NPOOL * NPOOL) + py * NPOOL) * C4 + c4;

    for (int px = 0; px < NPOOL; px++) {
        float4 m = make_float4(-FLT_MAX, -FLT_MAX, -FLT_MAX, -FLT_MAX);
#pragma unroll
        for (int i = 0; i < 2; i++) {
            const float xs = fmaf((float)(2 * px + i), sx, xb);
            const float gx = ((xs >= 0.0f) && (xs <= fw)) ? 1.0f : 0.0f;
            const float x0 = floorf(xs);
            const float wx = xs - x0;
            int xi = min(max((int)x0, 0), FW - 1);
            const int cA = xi * C4;
            const int cB = min(xi + 1, FW - 1) * C4;
            const float wxg   = wx * gx;
            const float omwxg = (1.0f - wx) * gx;

            // horizontal lerp per distinct feature row
            const float4 a0 = __ldg(fb + row0 + cA);
            const float4 b0 = __ldg(fb + row0 + cB);
            const float4 a1 = __ldg(fb + row1 + cA);
            const float4 b1 = __ldg(fb + row1 + cB);
            const float4 a3 = __ldg(fb + row3 + cA);
            const float4 b3 = __ldg(fb + row3 + cB);

            const float4 h0 = lerp4(a0, b0, omwxg, wxg);
            const float4 h1 = lerp4(a1, b1, omwxg, wxg);
            const float4 h3 = lerp4(a3, b3, omwxg, wxg);

            float4 h2;
            if (shared_row) {
                h2 = h1;
            } else {
                const float4 a2 = __ldg(fb + row2 + cA);
                const float4 b2 = __ldg(fb + row2 + cB);
                h2 = lerp4(a2, b2, omwxg, wxg);
            }

            const float4 v0 = lerp4(h0, h1, omwyg0, wyg0);
            const float4 v1 = lerp4(h2, h3, omwyg1, wyg1);
            maxacc4(m, v0, v1);
        }
        __stcs(&ob[px * C4], m);
    }
}

extern "C" void kernel_launch(void* const* d_in, const int* in_sizes, int n_in,
                              void* d_out, int out_size) {
    const float* fmap     = (const float*)d_in[0];
    const float* rois     = (const float*)d_in[1];
    const int*   img_size = (const int*)d_in[2];
    float* out = (float*)d_out;

    const int N = in_sizes[1] / 4;   // number of rois
    dim3 grid(NPOOL, N);
    roi_pool_kernel<<<grid, 128>>>(fmap, rois, img_size, out);
}